// round 4
// baseline (speedup 1.0000x reference)
#include <cuda_runtime.h>

// out[b,q,d] = sum_k values[b,k,d]  (softmax over singleton axis == 1;
// queries/keys/w_score are dead code). B=4, Q=512, K=512, F=128.
//
// R3 finding: redundant 256KB/block reads are L1tex-wavefront bound
// (2048 wavefronts/SM). This version: each block reads ONLY its 16KB
// K-slice (128 wavefronts), publishes a partial, cross-block spin-sync
// (all 64 blocks co-resident => safe), then reads 16 partials from L2
// and writes its broadcast output slice. One kernel, one launch.

#define B_ 4
#define Q_ 512
#define K_ 512
#define F4 32                     // float4 per row
#define SLICES 16                 // blocks per batch
#define THREADS 512

// Scratch (no allocation allowed): partials + sync counters.
__device__ float4 g_part[B_][SLICES][F4];   // 8 KB
__device__ int    g_cnt[B_];                // arrivals  (zero-init, reset each run)
__device__ int    g_fin[B_];                // finishers (zero-init, reset each run)

__global__ void __launch_bounds__(THREADS, 1)
fused_sum_broadcast(const float4* __restrict__ values, float4* __restrict__ out) {
    __shared__ float4 part[SLICES][F4];     // 8 KB

    const int b   = blockIdx.x >> 4;        // batch
    const int blk = blockIdx.x & 15;        // slice (K-slice AND Q-slice id)
    const int d4  = threadIdx.x & 31;       // float4 column
    const int rep = threadIdx.x >> 5;       // warp id

    // ---- Phase 1: sum this block's 32 K-rows (rows blk*32 .. +32).
    // Each thread: 2 independent LDG.128, one add.
    const float4* p = values + ((size_t)(b * K_ + blk * 32 + rep * 2)) * F4 + d4;
    float4 v0 = p[0];
    float4 v1 = p[F4];
    float4 a;
    a.x = v0.x + v1.x; a.y = v0.y + v1.y; a.z = v0.z + v1.z; a.w = v0.w + v1.w;
    part[rep][d4] = a;
    __syncthreads();

    // ---- Phase 2: warp 0 reduces 16 smem partials, publishes to global.
    if (rep == 0) {
        float4 s0 = part[0][d4], s1 = part[1][d4];
#pragma unroll
        for (int i = 2; i < SLICES; i += 2) {
            float4 w0 = part[i][d4];
            float4 w1 = part[i + 1][d4];
            s0.x += w0.x; s0.y += w0.y; s0.z += w0.z; s0.w += w0.w;
            s1.x += w1.x; s1.y += w1.y; s1.z += w1.z; s1.w += w1.w;
        }
        float4 t;
        t.x = s0.x + s1.x; t.y = s0.y + s1.y;
        t.z = s0.z + s1.z; t.w = s0.w + s1.w;
        g_part[b][blk][d4] = t;
        __threadfence();                    // partial visible before counter bump
    }
    __syncthreads();

    // ---- Phase 3: arrive + spin until all 16 slices of this batch published.
    if (threadIdx.x == 0) {
        atomicAdd(&g_cnt[b], 1);
        while (((volatile int*)g_cnt)[b] < SLICES) { }
        __threadfence();                    // acquire: order partial reads after flag
    }
    __syncthreads();

    // ---- Phase 4: every thread sums the 16 partials (L2, bypass L1).
    float4 s0 = __ldcg(&g_part[b][0][d4]);
    float4 s1 = __ldcg(&g_part[b][1][d4]);
#pragma unroll
    for (int i = 2; i < SLICES; i += 2) {
        float4 w0 = __ldcg(&g_part[b][i][d4]);
        float4 w1 = __ldcg(&g_part[b][i + 1][d4]);
        s0.x += w0.x; s0.y += w0.y; s0.z += w0.z; s0.w += w0.w;
        s1.x += w1.x; s1.y += w1.y; s1.z += w1.z; s1.w += w1.w;
    }
    float4 t;
    t.x = s0.x + s1.x; t.y = s0.y + s1.y;
    t.z = s0.z + s1.z; t.w = s0.w + s1.w;

    // ---- Phase 5: write this block's 32 broadcast Q-rows (2 STG.128/thread).
    float4* ob = out + ((size_t)(b * Q_ + blk * 32 + rep * 2)) * F4 + d4;
    ob[0]  = t;
    ob[F4] = t;

    // ---- Cleanup: last finisher of each batch resets counters for next replay.
    __syncthreads();
    if (threadIdx.x == 0) {
        int old = atomicAdd(&g_fin[b], 1);
        if (old == SLICES - 1) {
            g_cnt[b] = 0;
            g_fin[b] = 0;
        }
    }
}

extern "C" void kernel_launch(void* const* d_in, const int* in_sizes, int n_in,
                              void* d_out, int out_size) {
    // inputs (metadata order): queries, keys, values, w_score
    const float4* values = (const float4*)d_in[2];
    float4* out = (float4*)d_out;
    fused_sum_broadcast<<<B_ * SLICES, THREADS>>>(values, out);
}

// round 5
// speedup vs baseline: 1.2651x; 1.2651x over previous
#include <cuda_runtime.h>

// out[b,q,d] = sum_k values[b,k,d]  (softmax over singleton axis == 1;
// queries/keys/w_score are dead code). B=4, Q=512, K=512, F=128.
//
// R3/R4 findings: (a) redundant full-F reads are L1tex-wavefront bound
// (2048 wf/block); (b) any cross-block sync costs more than it saves at
// un-ramped clock. Fix: FEATURE-split. Each block sums all 512 K-rows of
// a 32-float column slice (1 wavefront per row = 512 wf, the floor) and
// broadcasts to a 64-row Q-slice. Blocks are fully independent.
// Grid = 4 batches x 4 f-slices x 8 q-slices = 128 blocks, 256 threads.

#define B_   4
#define Q_   512
#define K_   512
#define F4   32      // float4 per full row
#define FSL4 8       // float4 per feature slice (32 floats = 128 B)
#define QROWS 64     // Q rows per block

__global__ void __launch_bounds__(256, 1)
feat_split_sum_broadcast(const float4* __restrict__ values,
                         float4* __restrict__ out) {
    __shared__ float4 part[8][FSL4];     // per-warp partial per column

    const int b   = blockIdx.x >> 5;          // batch        (0..3)
    const int rem = blockIdx.x & 31;
    const int fsl = rem >> 3;                 // feature slice (0..3)
    const int qsl = rem & 7;                  // Q slice       (0..7)

    const int tid  = threadIdx.x;
    const int w    = tid >> 5;                // warp (0..7): K rows [w*64, w*64+64)
    const int lane = tid & 31;
    const int c    = lane & 7;                // column (float4) within slice
    const int rsub = lane >> 3;               // row offset 0..3 within a 4-row group

    // ---- Phase 1: warp w sums rows [w*64, (w+1)*64), 4 rows per LDG.128 group.
    // 16 independent LDG.128 per lane (front-batched), 4 accumulators.
    const float4* p = values
        + ((size_t)(b * K_ + w * 64 + rsub)) * F4 + fsl * FSL4 + c;

    float4 a0 = make_float4(0.f,0.f,0.f,0.f);
    float4 a1 = a0, a2 = a0, a3 = a0;
#pragma unroll
    for (int i = 0; i < 16; i += 4) {
        float4 v0 = p[(i + 0) * 4 * F4];
        float4 v1 = p[(i + 1) * 4 * F4];
        float4 v2 = p[(i + 2) * 4 * F4];
        float4 v3 = p[(i + 3) * 4 * F4];
        a0.x += v0.x; a0.y += v0.y; a0.z += v0.z; a0.w += v0.w;
        a1.x += v1.x; a1.y += v1.y; a1.z += v1.z; a1.w += v1.w;
        a2.x += v2.x; a2.y += v2.y; a2.z += v2.z; a2.w += v2.w;
        a3.x += v3.x; a3.y += v3.y; a3.z += v3.z; a3.w += v3.w;
    }
    float4 acc;
    acc.x = (a0.x + a1.x) + (a2.x + a3.x);
    acc.y = (a0.y + a1.y) + (a2.y + a3.y);
    acc.z = (a0.z + a1.z) + (a2.z + a3.z);
    acc.w = (a0.w + a1.w) + (a2.w + a3.w);

    // ---- Phase 2: reduce across the 4 lanes sharing a column (xor 8, 16).
#pragma unroll
    for (int m = 8; m <= 16; m <<= 1) {
        acc.x += __shfl_xor_sync(0xffffffffu, acc.x, m);
        acc.y += __shfl_xor_sync(0xffffffffu, acc.y, m);
        acc.z += __shfl_xor_sync(0xffffffffu, acc.z, m);
        acc.w += __shfl_xor_sync(0xffffffffu, acc.w, m);
    }
    if (lane < FSL4) part[w][lane] = acc;     // lane == column
    __syncthreads();

    // ---- Phase 3: every thread sums the 8 warp-partials for its column
    // (smem broadcast reads, conflict-free).
    float4 s0 = part[0][c], s1 = part[1][c];
#pragma unroll
    for (int i = 2; i < 8; i += 2) {
        float4 v0 = part[i][c];
        float4 v1 = part[i + 1][c];
        s0.x += v0.x; s0.y += v0.y; s0.z += v0.z; s0.w += v0.w;
        s1.x += v1.x; s1.y += v1.y; s1.z += v1.z; s1.w += v1.w;
    }
    float4 t;
    t.x = s0.x + s1.x; t.y = s0.y + s1.y;
    t.z = s0.z + s1.z; t.w = s0.w + s1.w;

    // ---- Phase 4: broadcast to this block's 64 Q-rows, feature slice fsl.
    // Thread t writes rows (tid/8) and (tid/8 + 32) at column c.
    const int r0 = qsl * QROWS + (tid >> 3);
    float4* ob = out + ((size_t)(b * Q_ + r0)) * F4 + fsl * FSL4 + c;
    ob[0]          = t;
    ob[32 * F4]    = t;   // +32 rows
}

extern "C" void kernel_launch(void* const* d_in, const int* in_sizes, int n_in,
                              void* d_out, int out_size) {
    // inputs (metadata order): queries, keys, values, w_score
    const float4* values = (const float4*)d_in[2];
    float4* out = (float4*)d_out;
    feat_split_sum_broadcast<<<B_ * 4 * 8, 256>>>(values, out);
}

// round 6
// speedup vs baseline: 1.3204x; 1.0437x over previous
#include <cuda_runtime.h>

// out[b,q,d] = sum_k values[b,k,d]  (softmax over singleton axis == 1;
// queries/keys/w_score are dead code). B=4, Q=512, K=512, F=128.
//
// Feature-split decomposition (512 load-wavefronts/block = the floor for a
// full-K column sum). R6: 512 threads/block (16 warps) to overlap the L1tex
// wavefront drain with the load-latency chain; exactly 1 LDG.128 x8 + 1
// STG.128 per thread; single barrier; __ldcg streaming loads.
// Grid = 4 batches x 4 f-slices x 8 q-slices = 128 blocks (one wave).

#define B_   4
#define Q_   512
#define K_   512
#define F4   32      // float4 per full feature row
#define FSL4 8       // float4 per feature slice (32 floats = 128 B)
#define QROWS 64     // Q rows written per block

__global__ void __launch_bounds__(512, 1)
feat_split_sum_broadcast(const float4* __restrict__ values,
                         float4* __restrict__ out) {
    __shared__ float4 part[16][FSL4];          // per-warp column partials (2 KB)

    const int b   = blockIdx.x >> 5;           // batch         (0..3)
    const int rem = blockIdx.x & 31;
    const int fsl = rem >> 3;                  // feature slice (0..3)
    const int qsl = rem & 7;                   // Q slice       (0..7)

    const int tid  = threadIdx.x;
    const int w    = tid >> 5;                 // warp 0..15: K rows [w*32, w*32+32)
    const int lane = tid & 31;
    const int c    = lane & 7;                 // float4 column within slice
    const int rsub = lane >> 3;                // row offset 0..3 in a 4-row group

    // ---- Phase 1: each lane streams 8 rows (stride 4) of its column.
    const float4* p = values
        + ((size_t)(b * K_ + w * 32 + rsub)) * F4 + fsl * FSL4 + c;

    float4 v0 = __ldcg(p + 0  * 4 * F4);
    float4 v1 = __ldcg(p + 1  * 4 * F4);
    float4 v2 = __ldcg(p + 2  * 4 * F4);
    float4 v3 = __ldcg(p + 3  * 4 * F4);
    float4 v4 = __ldcg(p + 4  * 4 * F4);
    float4 v5 = __ldcg(p + 5  * 4 * F4);
    float4 v6 = __ldcg(p + 6  * 4 * F4);
    float4 v7 = __ldcg(p + 7  * 4 * F4);

    float4 acc;   // depth-3 pairwise tree
    acc.x = ((v0.x + v1.x) + (v2.x + v3.x)) + ((v4.x + v5.x) + (v6.x + v7.x));
    acc.y = ((v0.y + v1.y) + (v2.y + v3.y)) + ((v4.y + v5.y) + (v6.y + v7.y));
    acc.z = ((v0.z + v1.z) + (v2.z + v3.z)) + ((v4.z + v5.z) + (v6.z + v7.z));
    acc.w = ((v0.w + v1.w) + (v2.w + v3.w)) + ((v4.w + v5.w) + (v6.w + v7.w));

    // ---- Phase 2: fold the 4 row-groups sharing a column (xor 8, 16).
#pragma unroll
    for (int m = 8; m <= 16; m <<= 1) {
        acc.x += __shfl_xor_sync(0xffffffffu, acc.x, m);
        acc.y += __shfl_xor_sync(0xffffffffu, acc.y, m);
        acc.z += __shfl_xor_sync(0xffffffffu, acc.z, m);
        acc.w += __shfl_xor_sync(0xffffffffu, acc.w, m);
    }
    if (lane < FSL4) part[w][lane] = acc;
    __syncthreads();

    // ---- Phase 3: every thread sums the 16 warp-partials for its column
    // (broadcast LDS, conflict-free; pairwise tree).
    float4 s0 = part[0][c], s1 = part[1][c], s2 = part[2][c], s3 = part[3][c];
#pragma unroll
    for (int i = 4; i < 16; i += 4) {
        float4 w0 = part[i + 0][c];
        float4 w1 = part[i + 1][c];
        float4 w2 = part[i + 2][c];
        float4 w3 = part[i + 3][c];
        s0.x += w0.x; s0.y += w0.y; s0.z += w0.z; s0.w += w0.w;
        s1.x += w1.x; s1.y += w1.y; s1.z += w1.z; s1.w += w1.w;
        s2.x += w2.x; s2.y += w2.y; s2.z += w2.z; s2.w += w2.w;
        s3.x += w3.x; s3.y += w3.y; s3.z += w3.z; s3.w += w3.w;
    }
    float4 t;
    t.x = (s0.x + s1.x) + (s2.x + s3.x);
    t.y = (s0.y + s1.y) + (s2.y + s3.y);
    t.z = (s0.z + s1.z) + (s2.z + s3.z);
    t.w = (s0.w + s1.w) + (s2.w + s3.w);

    // ---- Phase 4: broadcast. Exactly one STG.128 per thread:
    // row = tid/8 within this block's 64-row Q slice, column c.
    const int row = qsl * QROWS + (tid >> 3);
    out[((size_t)(b * Q_ + row)) * F4 + fsl * FSL4 + c] = t;
}

extern "C" void kernel_launch(void* const* d_in, const int* in_sizes, int n_in,
                              void* d_out, int out_size) {
    // inputs (metadata order): queries, keys, values, w_score
    const float4* values = (const float4*)d_in[2];
    float4* out = (float4*)d_out;
    feat_split_sum_broadcast<<<128, 512>>>(values, out);
}